// round 1
// baseline (speedup 1.0000x reference)
#include <cuda_runtime.h>

#define NPIX 786432
#define KER 9
#define CIN 16
#define COUT 16
#define TPB 256

typedef unsigned long long u64;

__device__ __forceinline__ u64 pack2(float lo, float hi) {
    u64 r; asm("mov.b64 %0, {%1, %2};" : "=l"(r) : "f"(lo), "f"(hi)); return r;
}
__device__ __forceinline__ void unpack2(u64 v, float& lo, float& hi) {
    asm("mov.b64 {%0, %1}, %2;" : "=f"(lo), "=f"(hi) : "l"(v));
}
// packed f32x2 fma: d.lo += a.lo*b.lo ; d.hi += a.hi*b.hi
__device__ __forceinline__ void fma2(u64& d, u64 a, u64 b) {
    asm("fma.rn.f32x2 %0, %1, %2, %0;" : "+l"(d) : "l"(a), "l"(b));
}

__global__ __launch_bounds__(TPB) void healpix_conv_kernel(
    const float* __restrict__ x,      // (2, NPIX, CIN)
    const int*   __restrict__ nb,     // (NPIX, KER)
    const float* __restrict__ w,      // (COUT, KER, CIN)
    const float* __restrict__ bias,   // (COUT,)
    float*       __restrict__ y)      // (2, NPIX, COUT)
{
    // w duplicated into (w,w) f32x2 pairs, layout [k][c][o] so the o-loop is
    // contiguous and warp-uniform (broadcast LDS, conflict-free). 18 KB.
    __shared__ u64 wdup[KER * CIN * COUT];

    const int tid = threadIdx.x;
    for (int i = tid; i < KER * CIN * COUT; i += TPB) {
        const int o = i & 15;
        const int c = (i >> 4) & 15;
        const int k = i >> 8;
        const float wv = w[(o * KER + k) * CIN + c];
        wdup[i] = pack2(wv, wv);
    }
    __syncthreads();

    const int n = blockIdx.x * TPB + tid;
    if (n >= NPIX) return;

    u64 acc[COUT];
    #pragma unroll
    for (int o = 0; o < COUT; o++) {
        const float bo = bias[o];
        acc[o] = pack2(bo, bo);
    }

    const float* xb1 = x + (size_t)NPIX * CIN;   // batch 1 base

    #pragma unroll 1
    for (int k = 0; k < KER; k++) {
        const int idx = nb[n * KER + k];
        if (idx >= NPIX) continue;               // zero-pad row: contributes nothing

        const float4* r0 = (const float4*)(x   + (size_t)idx * CIN);
        const float4* r1 = (const float4*)(xb1 + (size_t)idx * CIN);

        u64 xp[CIN];
        #pragma unroll
        for (int q = 0; q < 4; q++) {
            const float4 a = r0[q];
            const float4 b = r1[q];
            xp[q * 4 + 0] = pack2(a.x, b.x);
            xp[q * 4 + 1] = pack2(a.y, b.y);
            xp[q * 4 + 2] = pack2(a.z, b.z);
            xp[q * 4 + 3] = pack2(a.w, b.w);
        }

        const u64* wk = &wdup[k * CIN * COUT];
        #pragma unroll
        for (int c = 0; c < CIN; c++) {
            const u64 xv = xp[c];
            #pragma unroll
            for (int o = 0; o < COUT; o++) {
                fma2(acc[o], xv, wk[c * COUT + o]);
            }
        }
    }

    float out0[COUT], out1[COUT];
    #pragma unroll
    for (int o = 0; o < COUT; o++) unpack2(acc[o], out0[o], out1[o]);

    float4* yp0 = (float4*)(y + (size_t)n * COUT);
    float4* yp1 = (float4*)(y + (size_t)NPIX * COUT + (size_t)n * COUT);
    #pragma unroll
    for (int q = 0; q < 4; q++) {
        yp0[q] = make_float4(out0[q*4+0], out0[q*4+1], out0[q*4+2], out0[q*4+3]);
        yp1[q] = make_float4(out1[q*4+0], out1[q*4+1], out1[q*4+2], out1[q*4+3]);
    }
}

extern "C" void kernel_launch(void* const* d_in, const int* in_sizes, int n_in,
                              void* d_out, int out_size) {
    const float* x    = (const float*)d_in[0];
    const int*   nb   = (const int*)d_in[1];
    const float* w    = (const float*)d_in[2];
    const float* bias = (const float*)d_in[3];
    float*       y    = (float*)d_out;

    const int blocks = (NPIX + TPB - 1) / TPB;   // 3072
    healpix_conv_kernel<<<blocks, TPB>>>(x, nb, w, bias, y);
}